// round 16
// baseline (speedup 1.0000x reference)
#include <cuda_runtime.h>
#include <cuda_bf16.h>
#include <cstdint>

#define B_   2048
#define F_   128
#define E_   128
#define KH   8
#define O_   64
#define FOLD 0.0625f     // (alpha-1) * d_k^-0.5 folded into C
#define NIT  3           // Newton iterations (smart init; 4 proven at bf16 floor)

// ---------------- device scratch ----------------
// A in MMA-fragment order: [hp][wid][kt][lane][reg0..3] u32  (one uint4 per lane per kt)
__device__ __align__(16) uint32_t g_FH[4 * 8 * 8 * 32 * 4];   // 128 KB (hi)
__device__ __align__(16) uint32_t g_FL[4 * 8 * 8 * 32 * 4];   // 128 KB (lo)

// hp stride in uint4 units: 8 wids * 8 kts * 32 lanes
#define HP_STRIDE_U4 (8 * 8 * 32)

// smem: Xh [128][272B] + Xl [128][272B] (persist) + per-warp buf 8x132 f32 x 8 warps
#define XSTRIDE 272
#define XLOFF   (128 * XSTRIDE)
#define ATT_OFF (2 * 128 * XSTRIDE)          // 69632
#define WBUF_FLOATS (8 * 132)                // per-warp: 8 rows x 132
#define SM_TOTAL (ATT_OFF + 8 * WBUF_FLOATS * 4)   // 103424 B

__device__ __forceinline__ uint32_t smem_u32(const void* p) {
    uint32_t a;
    asm("{ .reg .u64 t; cvta.to.shared.u64 t, %1; cvt.u32.u64 %0, t; }" : "=r"(a) : "l"(p));
    return a;
}

__device__ __forceinline__ void mma_bf16(float* d, const uint4& a,
                                         uint32_t b0, uint32_t b1) {
    asm volatile("mma.sync.aligned.m16n8k16.row.col.f32.bf16.bf16.f32 "
                 "{%0,%1,%2,%3}, {%4,%5,%6,%7}, {%8,%9}, {%0,%1,%2,%3};"
                 : "+f"(d[0]), "+f"(d[1]), "+f"(d[2]), "+f"(d[3])
                 : "r"(a.x), "r"(a.y), "r"(a.z), "r"(a.w), "r"(b0), "r"(b1));
}

__device__ __forceinline__ void ldmx4(uint32_t& b0, uint32_t& b1, uint32_t& b2, uint32_t& b3,
                                      uint32_t addr) {
    asm volatile("ldmatrix.sync.aligned.m8n8.x4.shared.b16 {%0,%1,%2,%3}, [%4];"
                 : "=r"(b0), "=r"(b1), "=r"(b2), "=r"(b3) : "r"(addr));
}

// packed f32x2 helpers (base Blackwell ISA)
#define ADD2(d, a, b)  asm("add.rn.f32x2 %0, %1, %2;" : "=l"(d) : "l"(a), "l"(b))
#define MUL2(d, a, b)  asm("mul.rn.f32x2 %0, %1, %2;" : "=l"(d) : "l"(a), "l"(b))
#define FMA2ACC(d, a, b) asm("fma.rn.f32x2 %0, %1, %2, %0;" : "+l"(d) : "l"(a), "l"(b))
#define PACK2(d, lo, hi) asm("mov.b64 %0, {%1, %2};" : "=l"(d) : "f"(lo), "f"(hi))
#define UNPK2(lo, hi, s) asm("mov.b64 {%0, %1}, %2;" : "=f"(lo), "=f"(hi) : "l"(s))
#define ABSM 0x7fffffff7fffffffULL

// ---------------------------------------------------------------------------
// prep: C = FOLD * W*Q^T per head, bf16 hi/lo split, fragment order
// grid = 256 blocks (k, x-chunk of 4), 256 threads, 1 item/thread
// ---------------------------------------------------------------------------
#define QS_STRIDE 65
__global__ __launch_bounds__(256)
void prep_kernel(const float* __restrict__ W, const float* __restrict__ Q) {
    __shared__ float qs[64 * QS_STRIDE];   // [o][y], padded
    __shared__ float ws[4 * 64];           // [xl][y]
    const int tid = threadIdx.x;
    const int k   = blockIdx.x >> 5;
    const int x0  = (blockIdx.x & 31) * 4;

    for (int i = tid; i < 4096; i += 256)
        qs[(i >> 6) * QS_STRIDE + (i & 63)] = Q[k * 4096 + i];
    ws[tid] = W[(k * 128 + x0) * 64 + tid];
    __syncthreads();

    const int hp = k >> 1;
    const int mb = (k & 1) * 64;
    {
        int xl = tid >> 6, o = tid & 63;
        const float* wr = ws + xl * 64;
        const float* qr = qs + o * QS_STRIDE;
        float acc = 0.0f;
#pragma unroll
        for (int y = 0; y < 64; y++) acc = fmaf(wr[y], qr[y], acc);
        acc *= FOLD;
        __nv_bfloat16 h = __float2bfloat16(acc);
        __nv_bfloat16 l = __float2bfloat16(acc - __bfloat162float(h));

        const int m   = mb + o;
        const int x   = x0 + xl;
        const int wid = m >> 4, g = m & 7, pA = (m >> 3) & 1;
        const int kt  = x >> 4, xr = x & 15;
        const int hi8 = (xr >> 3) & 1, tg = (xr >> 1) & 3, half = x & 1;
        const int r    = pA + 2 * hi8;
        const int lane = g * 4 + tg;
        const int idx2 = ((((hp * 8 + wid) * 8 + kt) * 32 + lane) * 4 + r) * 2 + half;
        ((__nv_bfloat16*)g_FH)[idx2] = h;
        ((__nv_bfloat16*)g_FL)[idx2] = l;
    }
}

// ---------------------------------------------------------------------------
// main: one CTA per b; stage X once, loop 4 head-pairs with NO CTA barriers
// ---------------------------------------------------------------------------
__global__ __launch_bounds__(256, 2)
void main_kernel(const float* __restrict__ Xg, const float* __restrict__ Vg,
                 float* __restrict__ out) {
    extern __shared__ char smem[];
    const int tid  = threadIdx.x;
    const int wid  = tid >> 5;
    const int lane = tid & 31;
    const int b    = blockIdx.x;
    const int mw   = wid * 16;

    // ---- stage X[b]: fp32 -> bf16 hi/lo into smem (once per b) ----
    {
        const float4* Xb4 = (const float4*)(Xg + (size_t)b * F_ * E_);
#pragma unroll
        for (int i = tid; i < 4096; i += 256) {
            int row = i >> 5, c = i & 31;
            float4 v = Xb4[i];
            uint2 hi, lo;
            __nv_bfloat16 h0 = __float2bfloat16(v.x), h1 = __float2bfloat16(v.y);
            __nv_bfloat16 h2 = __float2bfloat16(v.z), h3 = __float2bfloat16(v.w);
            __nv_bfloat162 p01{h0, h1}, p23{h2, h3};
            hi.x = *(uint32_t*)&p01; hi.y = *(uint32_t*)&p23;
            __nv_bfloat162 l01{__float2bfloat16(v.x - __bfloat162float(h0)),
                               __float2bfloat16(v.y - __bfloat162float(h1))};
            __nv_bfloat162 l23{__float2bfloat16(v.z - __bfloat162float(h2)),
                               __float2bfloat16(v.w - __bfloat162float(h3))};
            lo.x = *(uint32_t*)&l01; lo.y = *(uint32_t*)&l23;
            *(uint2*)(smem + row * XSTRIDE + c * 8)         = hi;
            *(uint2*)(smem + XLOFF + row * XSTRIDE + c * 8) = lo;
        }
    }
    __syncthreads();   // only CTA-wide barrier; X is read-only afterwards

    const int g  = lane >> 2;
    const int tg = lane & 3;
    const int ln  = (lane & 7) + ((lane >> 4) << 3);
    const int lk8 = (lane >> 3) & 1;
    const uint32_t sbase = smem_u32(smem);
    float* wbuf = (float*)(smem + ATT_OFF) + wid * WBUF_FLOATS;   // warp-private
    const float4* V4 = (const float4*)Vg;
    float4* O4 = (float4*)out;

    // rolling A-fragment registers (prefetched across hp boundary)
    const uint4* FH4 = ((const uint4*)g_FH) + (wid * 8) * 32 + lane;   // hp=0 base
    const uint4* FL4 = ((const uint4*)g_FL) + (wid * 8) * 32 + lane;
    uint4 ah = FH4[0];
    uint4 al = FL4[0];

#pragma unroll 1
    for (int hp = 0; hp < 4; hp++) {
        // ---- MMA mainloop (ah/al enter preloaded with kt0 of this hp) ----
        float acc[16][4];
#pragma unroll
        for (int t = 0; t < 16; t++)
#pragma unroll
            for (int j = 0; j < 4; j++) acc[t][j] = 0.0f;

#pragma unroll
        for (int kt = 0; kt < 8; kt++) {
            const int ktn = (kt < 7) ? kt + 1 : 7;
            uint4 ahn = FH4[ktn * 32];
            uint4 aln = FL4[ktn * 32];
            uint32_t raddr = sbase + (uint32_t)(ln * XSTRIDE + (kt * 2 + lk8) * 16);
#pragma unroll
            for (int j = 0; j < 4; j++) {
                uint32_t r0a = raddr + (uint32_t)((2 * j) * 16 * XSTRIDE);
                uint32_t r1a = raddr + (uint32_t)((2 * j + 1) * 16 * XSTRIDE);
                uint32_t b0, b1, b2, b3, c0, c1, c2, c3;
                uint32_t lb0, lb1, lb2, lb3, lc0, lc1, lc2, lc3;
                ldmx4(b0, b1, b2, b3, r0a);
                ldmx4(lb0, lb1, lb2, lb3, r0a + (uint32_t)XLOFF);
                ldmx4(c0, c1, c2, c3, r1a);
                ldmx4(lc0, lc1, lc2, lc3, r1a + (uint32_t)XLOFF);
                float* A0 = acc[4 * j];
                float* A1 = acc[4 * j + 1];
                float* A2 = acc[4 * j + 2];
                float* A3 = acc[4 * j + 3];
                mma_bf16(A0, ah, b0, b1);
                mma_bf16(A1, ah, b2, b3);
                mma_bf16(A2, ah, c0, c1);
                mma_bf16(A3, ah, c2, c3);
                mma_bf16(A0, ah, lb0, lb1);
                mma_bf16(A1, ah, lb2, lb3);
                mma_bf16(A2, ah, lc0, lc1);
                mma_bf16(A3, ah, lc2, lc3);
                mma_bf16(A0, al, b0, b1);
                mma_bf16(A1, al, b2, b3);
                mma_bf16(A2, al, c0, c1);
                mma_bf16(A3, al, c2, c3);
            }
            ah = ahn;
            al = aln;
        }

        // ---- prefetch next hp's kt0 A-fragments (hidden under Newton) ----
        if (hp < 3) {
            FH4 += HP_STRIDE_U4;
            FL4 += HP_STRIDE_U4;
            ah = FH4[0];
            al = FL4[0];
        }

        // ---- row max (warp-local) ----
        float mA = acc[0][0], mB = acc[0][2];
#pragma unroll
        for (int t = 0; t < 16; t++) {
            mA = fmaxf(mA, fmaxf(acc[t][0], acc[t][1]));
            mB = fmaxf(mB, fmaxf(acc[t][2], acc[t][3]));
        }
        mA = fmaxf(mA, __shfl_xor_sync(0xffffffffu, mA, 1));
        mA = fmaxf(mA, __shfl_xor_sync(0xffffffffu, mA, 2));
        mB = fmaxf(mB, __shfl_xor_sync(0xffffffffu, mB, 1));
        mB = fmaxf(mB, __shfl_xor_sync(0xffffffffu, mB, 2));

        // ---- pack z into f32x2 + row moments S=Σz, Q=Σz² ----
        unsigned long long zA[16], zB[16];
        unsigned long long SA2 = 0, QA2 = 0, SB2 = 0, QB2 = 0;
#pragma unroll
        for (int t = 0; t < 16; t++) {
            PACK2(zA[t], acc[t][0], acc[t][1]);
            PACK2(zB[t], acc[t][2], acc[t][3]);
            ADD2(SA2, SA2, zA[t]);
            FMA2ACC(QA2, zA[t], zA[t]);
            ADD2(SB2, SB2, zB[t]);
            FMA2ACC(QB2, zB[t], zB[t]);
        }
        float SAll_A, QAll_A, SAll_B, QAll_B;
        {
            float a0, a1;
            UNPK2(a0, a1, SA2); SAll_A = a0 + a1;
            UNPK2(a0, a1, QA2); QAll_A = a0 + a1;
            UNPK2(a0, a1, SB2); SAll_B = a0 + a1;
            UNPK2(a0, a1, QB2); QAll_B = a0 + a1;
            SAll_A += __shfl_xor_sync(0xffffffffu, SAll_A, 1);
            SAll_A += __shfl_xor_sync(0xffffffffu, SAll_A, 2);
            QAll_A += __shfl_xor_sync(0xffffffffu, QAll_A, 1);
            QAll_A += __shfl_xor_sync(0xffffffffu, QAll_A, 2);
            SAll_B += __shfl_xor_sync(0xffffffffu, SAll_B, 1);
            SAll_B += __shfl_xor_sync(0xffffffffu, SAll_B, 2);
            QAll_B += __shfl_xor_sync(0xffffffffu, QAll_B, 1);
            QAll_B += __shfl_xor_sync(0xffffffffu, QAll_B, 2);
        }

        // ---- smart init: all-support closed form, clamped to safe bracket ----
        float tauA, tauB;
        {
            float DA = fmaxf(fmaf(SAll_A, SAll_A, -128.0f * (QAll_A - 1.0f)), 0.0f);
            float tqA = (SAll_A - sqrtf(DA)) * 0.0078125f;
            tauA = fmaxf(mA - 1.0f, fminf(tqA, mA - 0.0078125f));
            float DB = fmaxf(fmaf(SAll_B, SAll_B, -128.0f * (QAll_B - 1.0f)), 0.0f);
            float tqB = (SAll_B - sqrtf(DB)) * 0.0078125f;
            tauB = fmaxf(mB - 1.0f, fminf(tqB, mB - 0.0078125f));
        }

        // ---- packed Newton via moments: per elem only T += t|t|, Sb += |t| ----
#pragma unroll 1
        for (int it = 0; it < NIT; it++) {
            unsigned long long nA2, nB2;
            unsigned long long TA2 = 0, SbA2 = 0, TB2 = 0, SbB2 = 0;
            float ntA = -tauA, ntB = -tauB;
            PACK2(nA2, ntA, ntA);
            PACK2(nB2, ntB, ntB);
#pragma unroll
            for (int t = 0; t < 16; t++) {
                unsigned long long t2, a2;
                ADD2(t2, zA[t], nA2);
                a2 = t2 & ABSM;
                FMA2ACC(TA2, t2, a2);
                ADD2(SbA2, SbA2, a2);
                ADD2(t2, zB[t], nB2);
                a2 = t2 & ABSM;
                FMA2ACC(TB2, t2, a2);
                ADD2(SbB2, SbB2, a2);
            }
            float x0, x1;
            UNPK2(x0, x1, TA2);  float TA  = x0 + x1;
            UNPK2(x0, x1, SbA2); float SbA = x0 + x1;
            UNPK2(x0, x1, TB2);  float TB  = x0 + x1;
            UNPK2(x0, x1, SbB2); float SbB = x0 + x1;
            TA  += __shfl_xor_sync(0xffffffffu, TA, 1);
            TA  += __shfl_xor_sync(0xffffffffu, TA, 2);
            SbA += __shfl_xor_sync(0xffffffffu, SbA, 1);
            SbA += __shfl_xor_sync(0xffffffffu, SbA, 2);
            TB  += __shfl_xor_sync(0xffffffffu, TB, 1);
            TB  += __shfl_xor_sync(0xffffffffu, TB, 2);
            SbB += __shfl_xor_sync(0xffffffffu, SbB, 1);
            SbB += __shfl_xor_sync(0xffffffffu, SbB, 2);
            float sA = fmaf(-128.0f, tauA, SAll_A) + SbA;
            float qA = 2.0f * fmaf(fmaf(128.0f, tauA, -2.0f * SAll_A), tauA, QAll_A) + 2.0f * TA;
            float sB = fmaf(-128.0f, tauB, SAll_B) + SbB;
            float qB = 2.0f * fmaf(fmaf(128.0f, tauB, -2.0f * SAll_B), tauB, QAll_B) + 2.0f * TB;
            tauA += __fdividef(qA - 4.0f, 4.0f * sA);
            tauB += __fdividef(qB - 4.0f, 4.0f * sB);
        }

        // ---- final p = r'^2 (scale cancels), psum, inv ----
        float invA, invB;
        {
            unsigned long long nA2, nB2, pA2 = 0ULL, pB2 = 0ULL;
            float ntA = -tauA, ntB = -tauB;
            PACK2(nA2, ntA, ntA);
            PACK2(nB2, ntB, ntB);
#pragma unroll
            for (int t = 0; t < 16; t++) {
                unsigned long long t2, r2, p2;
                ADD2(t2, zA[t], nA2);
                r2 = t2 & ABSM;
                ADD2(r2, t2, r2);
                MUL2(p2, r2, r2);
                zA[t] = p2;
                ADD2(pA2, pA2, p2);
                ADD2(t2, zB[t], nB2);
                r2 = t2 & ABSM;
                ADD2(r2, t2, r2);
                MUL2(p2, r2, r2);
                zB[t] = p2;
                ADD2(pB2, pB2, p2);
            }
            float p0, p1;
            UNPK2(p0, p1, pA2); float psA = p0 + p1;
            UNPK2(p0, p1, pB2); float psB = p0 + p1;
            psA += __shfl_xor_sync(0xffffffffu, psA, 1);
            psA += __shfl_xor_sync(0xffffffffu, psA, 2);
            psB += __shfl_xor_sync(0xffffffffu, psB, 1);
            psB += __shfl_xor_sync(0xffffffffu, psB, 2);
            invA = __fdividef(1.0f, psA);
            invB = __fdividef(1.0f, psB);
        }

        // ---- warp-local transpose + store, chunk 0 (rows mw..mw+7, zA) ----
#pragma unroll
        for (int t = 0; t < 16; t++) {
            float f0, f1;
            UNPK2(f0, f1, zA[t]);
            *(float2*)(wbuf + g * 132 + t * 8 + 2 * tg) = make_float2(f0 * invA, f1 * invA);
        }
        __syncwarp();
#pragma unroll
        for (int r8 = 0; r8 < 8; r8++) {
            const int row = mw + r8;                 // 0..127
            float4 a = *(const float4*)(wbuf + r8 * 132 + lane * 4);
            float4 v = V4[(hp * 128 + row) * 32 + lane];
            const int kk = hp * 2 + (row >> 6), o = row & 63;
            float4 w;
            w.x = a.x * v.x; w.y = a.y * v.y; w.z = a.z * v.z; w.w = a.w * v.w;
            O4[(((size_t)b * KH + kk) * O_ + o) * 32 + lane] = w;
        }
        __syncwarp();

        // ---- chunk 1 (rows mw+8..mw+15, zB) ----
#pragma unroll
        for (int t = 0; t < 16; t++) {
            float f0, f1;
            UNPK2(f0, f1, zB[t]);
            *(float2*)(wbuf + g * 132 + t * 8 + 2 * tg) = make_float2(f0 * invB, f1 * invB);
        }
        __syncwarp();
#pragma unroll
        for (int r8 = 0; r8 < 8; r8++) {
            const int row = mw + 8 + r8;             // 0..127
            float4 a = *(const float4*)(wbuf + r8 * 132 + lane * 4);
            float4 v = V4[(hp * 128 + row) * 32 + lane];
            const int kk = hp * 2 + (row >> 6), o = row & 63;
            float4 w;
            w.x = a.x * v.x; w.y = a.y * v.y; w.z = a.z * v.z; w.w = a.w * v.w;
            O4[(((size_t)b * KH + kk) * O_ + o) * 32 + lane] = w;
        }
        __syncwarp();
    }
}

// ---------------------------------------------------------------------------
extern "C" void kernel_launch(void* const* d_in, const int* in_sizes, int n_in,
                              void* d_out, int out_size) {
    const float* x = (const float*)d_in[0];   // [2048,128,128]
    const float* w = (const float*)d_in[1];   // [8,128,64]
    const float* q = (const float*)d_in[2];   // [8,64,64]
    const float* v = (const float*)d_in[3];   // [8,64,128]
    float* out = (float*)d_out;               // [2048,8,64,128]

    cudaFuncSetAttribute(main_kernel, cudaFuncAttributeMaxDynamicSharedMemorySize, SM_TOTAL);

    prep_kernel<<<256, 256>>>(w, q);
    main_kernel<<<B_, 256, SM_TOTAL>>>(x, v, out);
}

// round 17
// speedup vs baseline: 1.5067x; 1.5067x over previous
#include <cuda_runtime.h>
#include <cuda_bf16.h>
#include <cstdint>

#define B_   2048
#define F_   128
#define E_   128
#define KH   8
#define O_   64
#define FOLD 0.0625f     // (alpha-1) * d_k^-0.5 folded into C
#define NIT  3           // Newton iterations (smart init; rel_err 4.3e-5 measured R16)

// ---------------- device scratch ----------------
// A in MMA-fragment order: [hp][wid][kt][lane][reg0..3] u32  (one uint4 per lane per kt)
__device__ __align__(16) uint32_t g_FH[4 * 8 * 8 * 32 * 4];   // 128 KB (hi)
__device__ __align__(16) uint32_t g_FL[4 * 8 * 8 * 32 * 4];   // 128 KB (lo)

// hp stride in uint4 units: 8 wids * 8 kts * 32 lanes
#define HP_STRIDE_U4 (8 * 8 * 32)

// smem: Xh [128][272B] + Xl [128][272B] (persist) + per-warp buf 8x132 f32 x 8 warps
#define XSTRIDE 272
#define XLOFF   (128 * XSTRIDE)
#define ATT_OFF (2 * 128 * XSTRIDE)          // 69632
#define WBUF_FLOATS (8 * 132)                // per-warp: 8 rows x 132
#define SM_TOTAL (ATT_OFF + 8 * WBUF_FLOATS * 4)   // 103424 B

__device__ __forceinline__ uint32_t smem_u32(const void* p) {
    uint32_t a;
    asm("{ .reg .u64 t; cvta.to.shared.u64 t, %1; cvt.u32.u64 %0, t; }" : "=r"(a) : "l"(p));
    return a;
}

__device__ __forceinline__ void mma_bf16(float* d, const uint4& a,
                                         uint32_t b0, uint32_t b1) {
    asm volatile("mma.sync.aligned.m16n8k16.row.col.f32.bf16.bf16.f32 "
                 "{%0,%1,%2,%3}, {%4,%5,%6,%7}, {%8,%9}, {%0,%1,%2,%3};"
                 : "+f"(d[0]), "+f"(d[1]), "+f"(d[2]), "+f"(d[3])
                 : "r"(a.x), "r"(a.y), "r"(a.z), "r"(a.w), "r"(b0), "r"(b1));
}

__device__ __forceinline__ void ldmx4(uint32_t& b0, uint32_t& b1, uint32_t& b2, uint32_t& b3,
                                      uint32_t addr) {
    asm volatile("ldmatrix.sync.aligned.m8n8.x4.shared.b16 {%0,%1,%2,%3}, [%4];"
                 : "=r"(b0), "=r"(b1), "=r"(b2), "=r"(b3) : "r"(addr));
}

// packed f32x2 helpers (base Blackwell ISA)
#define ADD2(d, a, b)  asm("add.rn.f32x2 %0, %1, %2;" : "=l"(d) : "l"(a), "l"(b))
#define MUL2(d, a, b)  asm("mul.rn.f32x2 %0, %1, %2;" : "=l"(d) : "l"(a), "l"(b))
#define FMA2ACC(d, a, b) asm("fma.rn.f32x2 %0, %1, %2, %0;" : "+l"(d) : "l"(a), "l"(b))
#define PACK2(d, lo, hi) asm("mov.b64 %0, {%1, %2};" : "=l"(d) : "f"(lo), "f"(hi))
#define UNPK2(lo, hi, s) asm("mov.b64 {%0, %1}, %2;" : "=f"(lo), "=f"(hi) : "l"(s))
#define ABSM 0x7fffffff7fffffffULL

// ---------------------------------------------------------------------------
// prep: C = FOLD * W*Q^T per head, bf16 hi/lo split, fragment order
// grid = 256 blocks (k, x-chunk of 4), 256 threads, 1 item/thread
// ---------------------------------------------------------------------------
#define QS_STRIDE 65
__global__ __launch_bounds__(256)
void prep_kernel(const float* __restrict__ W, const float* __restrict__ Q) {
    __shared__ float qs[64 * QS_STRIDE];   // [o][y], padded
    __shared__ float ws[4 * 64];           // [xl][y]
    const int tid = threadIdx.x;
    const int k   = blockIdx.x >> 5;
    const int x0  = (blockIdx.x & 31) * 4;

    for (int i = tid; i < 4096; i += 256)
        qs[(i >> 6) * QS_STRIDE + (i & 63)] = Q[k * 4096 + i];
    ws[tid] = W[(k * 128 + x0) * 64 + tid];
    __syncthreads();

    const int hp = k >> 1;
    const int mb = (k & 1) * 64;
    {
        int xl = tid >> 6, o = tid & 63;
        const float* wr = ws + xl * 64;
        const float* qr = qs + o * QS_STRIDE;
        float acc = 0.0f;
#pragma unroll
        for (int y = 0; y < 64; y++) acc = fmaf(wr[y], qr[y], acc);
        acc *= FOLD;
        __nv_bfloat16 h = __float2bfloat16(acc);
        __nv_bfloat16 l = __float2bfloat16(acc - __bfloat162float(h));

        const int m   = mb + o;
        const int x   = x0 + xl;
        const int wid = m >> 4, g = m & 7, pA = (m >> 3) & 1;
        const int kt  = x >> 4, xr = x & 15;
        const int hi8 = (xr >> 3) & 1, tg = (xr >> 1) & 3, half = x & 1;
        const int r    = pA + 2 * hi8;
        const int lane = g * 4 + tg;
        const int idx2 = ((((hp * 8 + wid) * 8 + kt) * 32 + lane) * 4 + r) * 2 + half;
        ((__nv_bfloat16*)g_FH)[idx2] = h;
        ((__nv_bfloat16*)g_FL)[idx2] = l;
    }
}

// ---------------------------------------------------------------------------
// main: one CTA per b; stage X once, loop 4 head-pairs with NO CTA barriers
// ---------------------------------------------------------------------------
__global__ __launch_bounds__(256, 2)
void main_kernel(const float* __restrict__ Xg, const float* __restrict__ Vg,
                 float* __restrict__ out) {
    extern __shared__ char smem[];
    const int tid  = threadIdx.x;
    const int wid  = tid >> 5;
    const int lane = tid & 31;
    const int b    = blockIdx.x;
    const int mw   = wid * 16;

    // ---- stage X[b]: fp32 -> bf16 hi/lo into smem (once per b) ----
    {
        const float4* Xb4 = (const float4*)(Xg + (size_t)b * F_ * E_);
#pragma unroll
        for (int i = tid; i < 4096; i += 256) {
            int row = i >> 5, c = i & 31;
            float4 v = Xb4[i];
            uint2 hi, lo;
            __nv_bfloat16 h0 = __float2bfloat16(v.x), h1 = __float2bfloat16(v.y);
            __nv_bfloat16 h2 = __float2bfloat16(v.z), h3 = __float2bfloat16(v.w);
            __nv_bfloat162 p01{h0, h1}, p23{h2, h3};
            hi.x = *(uint32_t*)&p01; hi.y = *(uint32_t*)&p23;
            __nv_bfloat162 l01{__float2bfloat16(v.x - __bfloat162float(h0)),
                               __float2bfloat16(v.y - __bfloat162float(h1))};
            __nv_bfloat162 l23{__float2bfloat16(v.z - __bfloat162float(h2)),
                               __float2bfloat16(v.w - __bfloat162float(h3))};
            lo.x = *(uint32_t*)&l01; lo.y = *(uint32_t*)&l23;
            *(uint2*)(smem + row * XSTRIDE + c * 8)         = hi;
            *(uint2*)(smem + XLOFF + row * XSTRIDE + c * 8) = lo;
        }
    }
    __syncthreads();   // only CTA-wide barrier; X is read-only afterwards

    const int g  = lane >> 2;
    const int tg = lane & 3;
    const int ln  = (lane & 7) + ((lane >> 4) << 3);
    const int lk8 = (lane >> 3) & 1;
    const uint32_t sbase = smem_u32(smem);
    float* wbuf = (float*)(smem + ATT_OFF) + wid * WBUF_FLOATS;   // warp-private
    const float4* V4 = (const float4*)Vg;
    float4* O4 = (float4*)out;

    // rolling A-fragment registers (prefetched across hp boundary)
    const uint4* FH4 = ((const uint4*)g_FH) + (wid * 8) * 32 + lane;   // hp=0 base
    const uint4* FL4 = ((const uint4*)g_FL) + (wid * 8) * 32 + lane;
    uint4 ah = FH4[0];
    uint4 al = FL4[0];

#pragma unroll 1
    for (int hp = 0; hp < 4; hp++) {
        // ---- MMA mainloop (ah/al enter preloaded with kt0 of this hp) ----
        float acc[16][4];
#pragma unroll
        for (int t = 0; t < 16; t++)
#pragma unroll
            for (int j = 0; j < 4; j++) acc[t][j] = 0.0f;

#pragma unroll
        for (int kt = 0; kt < 8; kt++) {
            const int ktn = (kt < 7) ? kt + 1 : 7;
            uint4 ahn = FH4[ktn * 32];
            uint4 aln = FL4[ktn * 32];
            uint32_t raddr = sbase + (uint32_t)(ln * XSTRIDE + (kt * 2 + lk8) * 16);
#pragma unroll
            for (int j = 0; j < 4; j++) {
                uint32_t r0a = raddr + (uint32_t)((2 * j) * 16 * XSTRIDE);
                uint32_t r1a = raddr + (uint32_t)((2 * j + 1) * 16 * XSTRIDE);
                uint32_t b0, b1, b2, b3, c0, c1, c2, c3;
                uint32_t lb0, lb1, lb2, lb3, lc0, lc1, lc2, lc3;
                ldmx4(b0, b1, b2, b3, r0a);
                ldmx4(lb0, lb1, lb2, lb3, r0a + (uint32_t)XLOFF);
                ldmx4(c0, c1, c2, c3, r1a);
                ldmx4(lc0, lc1, lc2, lc3, r1a + (uint32_t)XLOFF);
                float* A0 = acc[4 * j];
                float* A1 = acc[4 * j + 1];
                float* A2 = acc[4 * j + 2];
                float* A3 = acc[4 * j + 3];
                mma_bf16(A0, ah, b0, b1);
                mma_bf16(A1, ah, b2, b3);
                mma_bf16(A2, ah, c0, c1);
                mma_bf16(A3, ah, c2, c3);
                mma_bf16(A0, ah, lb0, lb1);
                mma_bf16(A1, ah, lb2, lb3);
                mma_bf16(A2, ah, lc0, lc1);
                mma_bf16(A3, ah, lc2, lc3);
                mma_bf16(A0, al, b0, b1);
                mma_bf16(A1, al, b2, b3);
                mma_bf16(A2, al, c0, c1);
                mma_bf16(A3, al, c2, c3);
            }
            ah = ahn;
            al = aln;
        }

        // ---- prefetch next hp's kt0 A-fragments (hidden under Newton) ----
        if (hp < 3) {
            FH4 += HP_STRIDE_U4;
            FL4 += HP_STRIDE_U4;
            ah = FH4[0];
            al = FL4[0];
        }

        // ---- row max (warp-local) ----
        float mA = acc[0][0], mB = acc[0][2];
#pragma unroll
        for (int t = 0; t < 16; t++) {
            mA = fmaxf(mA, fmaxf(acc[t][0], acc[t][1]));
            mB = fmaxf(mB, fmaxf(acc[t][2], acc[t][3]));
        }
        mA = fmaxf(mA, __shfl_xor_sync(0xffffffffu, mA, 1));
        mA = fmaxf(mA, __shfl_xor_sync(0xffffffffu, mA, 2));
        mB = fmaxf(mB, __shfl_xor_sync(0xffffffffu, mB, 1));
        mB = fmaxf(mB, __shfl_xor_sync(0xffffffffu, mB, 2));

        // ---- pack z into f32x2 + row moments S=Σz, Q=Σz² ----
        unsigned long long zA[16], zB[16];
        unsigned long long SA2 = 0, QA2 = 0, SB2 = 0, QB2 = 0;
#pragma unroll
        for (int t = 0; t < 16; t++) {
            PACK2(zA[t], acc[t][0], acc[t][1]);
            PACK2(zB[t], acc[t][2], acc[t][3]);
            ADD2(SA2, SA2, zA[t]);
            FMA2ACC(QA2, zA[t], zA[t]);
            ADD2(SB2, SB2, zB[t]);
            FMA2ACC(QB2, zB[t], zB[t]);
        }
        float SAll_A, QAll_A, SAll_B, QAll_B;
        {
            float a0, a1;
            UNPK2(a0, a1, SA2); SAll_A = a0 + a1;
            UNPK2(a0, a1, QA2); QAll_A = a0 + a1;
            UNPK2(a0, a1, SB2); SAll_B = a0 + a1;
            UNPK2(a0, a1, QB2); QAll_B = a0 + a1;
            SAll_A += __shfl_xor_sync(0xffffffffu, SAll_A, 1);
            SAll_A += __shfl_xor_sync(0xffffffffu, SAll_A, 2);
            QAll_A += __shfl_xor_sync(0xffffffffu, QAll_A, 1);
            QAll_A += __shfl_xor_sync(0xffffffffu, QAll_A, 2);
            SAll_B += __shfl_xor_sync(0xffffffffu, SAll_B, 1);
            SAll_B += __shfl_xor_sync(0xffffffffu, SAll_B, 2);
            QAll_B += __shfl_xor_sync(0xffffffffu, QAll_B, 1);
            QAll_B += __shfl_xor_sync(0xffffffffu, QAll_B, 2);
        }

        // ---- smart init: all-support closed form, clamped to safe bracket ----
        float tauA, tauB;
        {
            float DA = fmaxf(fmaf(SAll_A, SAll_A, -128.0f * (QAll_A - 1.0f)), 0.0f);
            float tqA = (SAll_A - sqrtf(DA)) * 0.0078125f;
            tauA = fmaxf(mA - 1.0f, fminf(tqA, mA - 0.0078125f));
            float DB = fmaxf(fmaf(SAll_B, SAll_B, -128.0f * (QAll_B - 1.0f)), 0.0f);
            float tqB = (SAll_B - sqrtf(DB)) * 0.0078125f;
            tauB = fmaxf(mB - 1.0f, fminf(tqB, mB - 0.0078125f));
        }

        // ---- packed Newton via moments: per elem only T += t|t|, Sb += |t| ----
#pragma unroll 1
        for (int it = 0; it < NIT; it++) {
            unsigned long long nA2, nB2;
            unsigned long long TA2 = 0, SbA2 = 0, TB2 = 0, SbB2 = 0;
            float ntA = -tauA, ntB = -tauB;
            PACK2(nA2, ntA, ntA);
            PACK2(nB2, ntB, ntB);
#pragma unroll
            for (int t = 0; t < 16; t++) {
                unsigned long long t2, a2;
                ADD2(t2, zA[t], nA2);
                a2 = t2 & ABSM;
                FMA2ACC(TA2, t2, a2);
                ADD2(SbA2, SbA2, a2);
                ADD2(t2, zB[t], nB2);
                a2 = t2 & ABSM;
                FMA2ACC(TB2, t2, a2);
                ADD2(SbB2, SbB2, a2);
            }
            float x0, x1;
            UNPK2(x0, x1, TA2);  float TA  = x0 + x1;
            UNPK2(x0, x1, SbA2); float SbA = x0 + x1;
            UNPK2(x0, x1, TB2);  float TB  = x0 + x1;
            UNPK2(x0, x1, SbB2); float SbB = x0 + x1;
            TA  += __shfl_xor_sync(0xffffffffu, TA, 1);
            TA  += __shfl_xor_sync(0xffffffffu, TA, 2);
            SbA += __shfl_xor_sync(0xffffffffu, SbA, 1);
            SbA += __shfl_xor_sync(0xffffffffu, SbA, 2);
            TB  += __shfl_xor_sync(0xffffffffu, TB, 1);
            TB  += __shfl_xor_sync(0xffffffffu, TB, 2);
            SbB += __shfl_xor_sync(0xffffffffu, SbB, 1);
            SbB += __shfl_xor_sync(0xffffffffu, SbB, 2);
            float sA = fmaf(-128.0f, tauA, SAll_A) + SbA;
            float qA = 2.0f * fmaf(fmaf(128.0f, tauA, -2.0f * SAll_A), tauA, QAll_A) + 2.0f * TA;
            float sB = fmaf(-128.0f, tauB, SAll_B) + SbB;
            float qB = 2.0f * fmaf(fmaf(128.0f, tauB, -2.0f * SAll_B), tauB, QAll_B) + 2.0f * TB;
            tauA += __fdividef(qA - 4.0f, 4.0f * sA);
            tauB += __fdividef(qB - 4.0f, 4.0f * sB);
        }

        // ---- final p = r'^2 (scale cancels), psum, inv ----
        float invA, invB;
        {
            unsigned long long nA2, nB2, pA2 = 0ULL, pB2 = 0ULL;
            float ntA = -tauA, ntB = -tauB;
            PACK2(nA2, ntA, ntA);
            PACK2(nB2, ntB, ntB);
#pragma unroll
            for (int t = 0; t < 16; t++) {
                unsigned long long t2, r2, p2;
                ADD2(t2, zA[t], nA2);
                r2 = t2 & ABSM;
                ADD2(r2, t2, r2);
                MUL2(p2, r2, r2);
                zA[t] = p2;
                ADD2(pA2, pA2, p2);
                ADD2(t2, zB[t], nB2);
                r2 = t2 & ABSM;
                ADD2(r2, t2, r2);
                MUL2(p2, r2, r2);
                zB[t] = p2;
                ADD2(pB2, pB2, p2);
            }
            float p0, p1;
            UNPK2(p0, p1, pA2); float psA = p0 + p1;
            UNPK2(p0, p1, pB2); float psB = p0 + p1;
            psA += __shfl_xor_sync(0xffffffffu, psA, 1);
            psA += __shfl_xor_sync(0xffffffffu, psA, 2);
            psB += __shfl_xor_sync(0xffffffffu, psB, 1);
            psB += __shfl_xor_sync(0xffffffffu, psB, 2);
            invA = __fdividef(1.0f, psA);
            invB = __fdividef(1.0f, psB);
        }

        // ---- warp-local transpose + store, chunk 0 (rows mw..mw+7, zA) ----
#pragma unroll
        for (int t = 0; t < 16; t++) {
            float f0, f1;
            UNPK2(f0, f1, zA[t]);
            *(float2*)(wbuf + g * 132 + t * 8 + 2 * tg) = make_float2(f0 * invA, f1 * invA);
        }
        __syncwarp();
#pragma unroll
        for (int r8 = 0; r8 < 8; r8++) {
            const int row = mw + r8;                 // 0..127
            float4 a = *(const float4*)(wbuf + r8 * 132 + lane * 4);
            float4 v = V4[(hp * 128 + row) * 32 + lane];
            const int kk = hp * 2 + (row >> 6), o = row & 63;
            float4 w;
            w.x = a.x * v.x; w.y = a.y * v.y; w.z = a.z * v.z; w.w = a.w * v.w;
            O4[(((size_t)b * KH + kk) * O_ + o) * 32 + lane] = w;
        }
        __syncwarp();

        // ---- chunk 1 (rows mw+8..mw+15, zB) ----
#pragma unroll
        for (int t = 0; t < 16; t++) {
            float f0, f1;
            UNPK2(f0, f1, zB[t]);
            *(float2*)(wbuf + g * 132 + t * 8 + 2 * tg) = make_float2(f0 * invB, f1 * invB);
        }
        __syncwarp();
#pragma unroll
        for (int r8 = 0; r8 < 8; r8++) {
            const int row = mw + 8 + r8;             // 0..127
            float4 a = *(const float4*)(wbuf + r8 * 132 + lane * 4);
            float4 v = V4[(hp * 128 + row) * 32 + lane];
            const int kk = hp * 2 + (row >> 6), o = row & 63;
            float4 w;
            w.x = a.x * v.x; w.y = a.y * v.y; w.z = a.z * v.z; w.w = a.w * v.w;
            O4[(((size_t)b * KH + kk) * O_ + o) * 32 + lane] = w;
        }
        __syncwarp();
    }
}

// ---------------------------------------------------------------------------
extern "C" void kernel_launch(void* const* d_in, const int* in_sizes, int n_in,
                              void* d_out, int out_size) {
    const float* x = (const float*)d_in[0];   // [2048,128,128]
    const float* w = (const float*)d_in[1];   // [8,128,64]
    const float* q = (const float*)d_in[2];   // [8,64,64]
    const float* v = (const float*)d_in[3];   // [8,64,128]
    float* out = (float*)d_out;               // [2048,8,64,128]

    cudaFuncSetAttribute(main_kernel, cudaFuncAttributeMaxDynamicSharedMemorySize, SM_TOTAL);

    prep_kernel<<<256, 256>>>(w, q);
    main_kernel<<<B_, 256, SM_TOTAL>>>(x, v, out);
}